// round 14
// baseline (speedup 1.0000x reference)
#include <cuda_runtime.h>
#include <cuda_fp16.h>
#include <math.h>
#include <stdint.h>

#define D_MODEL 256
#define N_HEADS 8
#define HEAD_DIM 32
#define BATCH 8
#define SEQ 2048
#define M_TOTAL (BATCH * SEQ)  // 16384

// Scratch (alloc-free rule: __device__ globals)
__device__ __half g_Qh[M_TOTAL * D_MODEL];
__device__ __half g_Kh[M_TOTAL * D_MODEL];   // compacted keys
__device__ __half g_Vh[M_TOTAL * D_MODEL];   // compacted values
__device__ __half g_Oh[M_TOTAL * D_MODEL];
__device__ int g_pos[SEQ];
__device__ int g_cnt[1];
// Precomputed W fragments: [mat][nb][ks][nc][lane], uint4 = (hi[p0],lo[p0],hi[p0+4],lo[p0+4])
__device__ uint4 g_Wp[4 * 4 * 16 * 8 * 32];
#define WP_MAT_STRIDE (4 * 16 * 8 * 32)

// ---------------------------------------------------------------------------
// helpers
// ---------------------------------------------------------------------------
__device__ __forceinline__ void mma_f16(float* c, uint32_t a0, uint32_t a1,
                                        uint32_t a2, uint32_t a3,
                                        uint32_t b0, uint32_t b1) {
    asm volatile(
        "mma.sync.aligned.m16n8k16.row.col.f32.f16.f16.f32 "
        "{%0,%1,%2,%3}, {%4,%5,%6,%7}, {%8,%9}, {%0,%1,%2,%3};"
        : "+f"(c[0]), "+f"(c[1]), "+f"(c[2]), "+f"(c[3])
        : "r"(a0), "r"(a1), "r"(a2), "r"(a3), "r"(b0), "r"(b1));
}

__device__ __forceinline__ uint32_t pack_f16(float lo, float hi) {
    uint32_t r;
    asm("cvt.rn.f16x2.f32 %0, %1, %2;" : "=r"(r) : "f"(hi), "f"(lo));
    return r;
}

__device__ __forceinline__ float ex2(float x) {
    float r;
    asm("ex2.approx.ftz.f32 %0, %1;" : "=f"(r) : "f"(x));
    return r;
}

// multiply fp16x2 by 2^-10
__device__ __forceinline__ uint32_t hscale_dn10(uint32_t x) {
    uint32_t r;
    asm("mul.rn.f16x2 %0, %1, %2;" : "=r"(r) : "r"(x), "r"(0x14001400u));
    return r;
}

// ---------------------------------------------------------------------------
// Mask scan
// ---------------------------------------------------------------------------
__global__ __launch_bounds__(256) void scan_mask(const float* __restrict__ m,
                                                 int* __restrict__ pos,
                                                 int* __restrict__ cnt) {
    __shared__ int warpsum[8];
    const int tid = threadIdx.x;
    int keep[8], local[8], s = 0;
#pragma unroll
    for (int i = 0; i < 8; i++) {
        keep[i] = (m[tid * 8 + i] == 0.0f) ? 1 : 0;
        local[i] = s;
        s += keep[i];
    }
    const int lane = tid & 31, w = tid >> 5;
    int x = s;
#pragma unroll
    for (int d = 1; d < 32; d <<= 1) {
        int y = __shfl_up_sync(0xffffffffu, x, d);
        if (lane >= d) x += y;
    }
    if (lane == 31) warpsum[w] = x;
    __syncthreads();
    if (tid == 0) {
        int a = 0;
#pragma unroll
        for (int i = 0; i < 8; i++) {
            int t = warpsum[i];
            warpsum[i] = a;
            a += t;
        }
        *cnt = a;
    }
    __syncthreads();
    const int off = warpsum[w] + x - s;
#pragma unroll
    for (int i = 0; i < 8; i++)
        pos[tid * 8 + i] = keep[i] ? off + local[i] : -1;
}

// ---------------------------------------------------------------------------
// prep_w: split all 4 weight matrices into fragment-ordered (hi, lo*2^10)
// uint4 records. Thread = (mat, k-pair p, column n): n-coalesced loads.
// ---------------------------------------------------------------------------
__global__ __launch_bounds__(256) void prep_w(const float* __restrict__ wq,
                                              const float* __restrict__ wk,
                                              const float* __restrict__ wv,
                                              const float* __restrict__ wo,
                                              uint4* __restrict__ Wp) {
    int idx = blockIdx.x * 256 + threadIdx.x;  // 0..131071
    int mat = idx >> 15;
    int rem = idx & 32767;
    int p = rem >> 8;    // k-pair 0..127
    int n = rem & 255;   // column
    const float* W = (mat == 0) ? wq : (mat == 1) ? wk : (mat == 2) ? wv : wo;
    float w0 = W[(size_t)(2 * p) * 256 + n];
    float w1 = W[(size_t)(2 * p + 1) * 256 + n];
    uint32_t hip = pack_f16(w0, w1);
    __half2 hh = *(__half2*)&hip;
    uint32_t lop = pack_f16((w0 - __half2float(hh.x)) * 1024.0f,
                            (w1 - __half2float(hh.y)) * 1024.0f);
    int ks = p >> 3, q = p & 7;
    int tg = q & 3, sel = q >> 2;
    int nb = n >> 6, nc = (n >> 3) & 7, g = n & 7;
    int lanew = 4 * g + tg;
    uint2* dst = (uint2*)&Wp[(((mat * 4 + nb) * 16 + ks) * 8 + nc) * 32 + lanew];
    dst[sel] = make_uint2(hip, lop);
}

// ---------------------------------------------------------------------------
// Fused QKV projection GEMM, smem-free. blockIdx.z = matrix (0=Q,1=K,2=V).
// ---------------------------------------------------------------------------
__global__ __launch_bounds__(128) void gemm_qkv(
    const float* __restrict__ q, const float* __restrict__ k,
    const float* __restrict__ v, const uint4* __restrict__ Wp,
    const float* __restrict__ bq, const float* __restrict__ bk,
    const float* __restrict__ bv, __half* __restrict__ Cq,
    __half* __restrict__ Ck, __half* __restrict__ Cv,
    const int* __restrict__ remap_kv, float qscale) {
    const int mat = blockIdx.z;
    const float* A = (mat == 0) ? q : (mat == 1) ? k : v;
    const float* bias = (mat == 0) ? bq : (mat == 1) ? bk : bv;
    __half* C = (mat == 0) ? Cq : (mat == 1) ? Ck : Cv;
    const int* remap = (mat == 0) ? (const int*)nullptr : remap_kv;
    const float alpha = (mat == 0) ? qscale : 1.0f;

    const int tid = threadIdx.x;
    const int lane = tid & 31;
    const int wid = tid >> 5;
    const int g = lane >> 2;
    const int tg = lane & 3;
    const int m0 = blockIdx.y * 128;
    const int n0 = blockIdx.x * 64;

    const uint4* wp = Wp + (size_t)mat * WP_MAT_STRIDE +
                      (size_t)blockIdx.x * (16 * 8 * 32) + lane;
    const float* ap0 = A + (size_t)(m0 + wid * 32 + g) * 256 + 2 * tg;
    const float* ap1 = ap0 + 8 * 256;
    const float* ap2 = ap0 + 16 * 256;
    const float* ap3 = ap0 + 24 * 256;

    float acc[2][8][4];
#pragma unroll
    for (int f = 0; f < 2; f++)
#pragma unroll
        for (int nc = 0; nc < 8; nc++)
#pragma unroll
            for (int i = 0; i < 4; i++) acc[f][nc][i] = 0.f;

#pragma unroll 4
    for (int ks = 0; ks < 16; ks++) {
        uint32_t a[2][4], sa[2][4];
        {
            float2 x0 = *(const float2*)(ap0 + ks * 16);
            float2 x1 = *(const float2*)(ap1 + ks * 16);
            float2 x2 = *(const float2*)(ap0 + ks * 16 + 8);
            float2 x3 = *(const float2*)(ap1 + ks * 16 + 8);
            a[0][0] = pack_f16(x0.x, x0.y);
            a[0][1] = pack_f16(x1.x, x1.y);
            a[0][2] = pack_f16(x2.x, x2.y);
            a[0][3] = pack_f16(x3.x, x3.y);
            float2 y0 = *(const float2*)(ap2 + ks * 16);
            float2 y1 = *(const float2*)(ap3 + ks * 16);
            float2 y2 = *(const float2*)(ap2 + ks * 16 + 8);
            float2 y3 = *(const float2*)(ap3 + ks * 16 + 8);
            a[1][0] = pack_f16(y0.x, y0.y);
            a[1][1] = pack_f16(y1.x, y1.y);
            a[1][2] = pack_f16(y2.x, y2.y);
            a[1][3] = pack_f16(y3.x, y3.y);
        }
#pragma unroll
        for (int f = 0; f < 2; f++)
#pragma unroll
            for (int i = 0; i < 4; i++) sa[f][i] = hscale_dn10(a[f][i]);

#pragma unroll
        for (int nc = 0; nc < 8; nc++) {
            uint4 w = wp[(ks * 8 + nc) * 32];
#pragma unroll
            for (int f = 0; f < 2; f++) {
                mma_f16(acc[f][nc], sa[f][0], sa[f][1], sa[f][2], sa[f][3],
                        w.y, w.w);
                mma_f16(acc[f][nc], a[f][0], a[f][1], a[f][2], a[f][3],
                        w.x, w.z);
            }
        }
    }

#pragma unroll
    for (int f = 0; f < 2; f++) {
        int r0 = m0 + wid * 32 + f * 16 + g;
        int r1 = r0 + 8;
        int d0 = r0, d1 = r1;
        bool st0 = true, st1 = true;
        if (remap) {
            int p0 = __ldg(remap + (r0 & (SEQ - 1)));
            int p1 = __ldg(remap + (r1 & (SEQ - 1)));
            st0 = p0 >= 0;
            st1 = p1 >= 0;
            d0 = (r0 & ~(SEQ - 1)) + p0;
            d1 = (r1 & ~(SEQ - 1)) + p1;
        }
#pragma unroll
        for (int nc = 0; nc < 8; nc++) {
            int col = n0 + nc * 8 + tg * 2;
            float2 bv2 = *(const float2*)(bias + col);
            if (st0)
                *(uint32_t*)(C + (size_t)d0 * 256 + col) =
                    pack_f16((acc[f][nc][0] + bv2.x) * alpha,
                             (acc[f][nc][1] + bv2.y) * alpha);
            if (st1)
                *(uint32_t*)(C + (size_t)d1 * 256 + col) =
                    pack_f16((acc[f][nc][2] + bv2.x) * alpha,
                             (acc[f][nc][3] + bv2.y) * alpha);
        }
    }
}

// ---------------------------------------------------------------------------
// Output projection GEMM, smem-free: A fp16 direct loads -> C fp32.
// ---------------------------------------------------------------------------
__global__ __launch_bounds__(128) void gemm_out(const __half* __restrict__ A,
                                                const uint4* __restrict__ Wp,
                                                const float* __restrict__ bias,
                                                float* __restrict__ C) {
    const int tid = threadIdx.x;
    const int lane = tid & 31;
    const int wid = tid >> 5;
    const int g = lane >> 2;
    const int tg = lane & 3;
    const int m0 = blockIdx.y * 128;
    const int n0 = blockIdx.x * 64;

    const uint4* wp = Wp + (size_t)blockIdx.x * (16 * 8 * 32) + lane;
    const __half* ap0 = A + (size_t)(m0 + wid * 32 + g) * 256 + 2 * tg;
    const __half* ap1 = ap0 + 8 * 256;
    const __half* ap2 = ap0 + 16 * 256;
    const __half* ap3 = ap0 + 24 * 256;

    float acc[2][8][4];
#pragma unroll
    for (int f = 0; f < 2; f++)
#pragma unroll
        for (int nc = 0; nc < 8; nc++)
#pragma unroll
            for (int i = 0; i < 4; i++) acc[f][nc][i] = 0.f;

#pragma unroll 4
    for (int ks = 0; ks < 16; ks++) {
        uint32_t a[2][4], sa[2][4];
        a[0][0] = *(const uint32_t*)(ap0 + ks * 16);
        a[0][1] = *(const uint32_t*)(ap1 + ks * 16);
        a[0][2] = *(const uint32_t*)(ap0 + ks * 16 + 8);
        a[0][3] = *(const uint32_t*)(ap1 + ks * 16 + 8);
        a[1][0] = *(const uint32_t*)(ap2 + ks * 16);
        a[1][1] = *(const uint32_t*)(ap3 + ks * 16);
        a[1][2] = *(const uint32_t*)(ap2 + ks * 16 + 8);
        a[1][3] = *(const uint32_t*)(ap3 + ks * 16 + 8);
#pragma unroll
        for (int f = 0; f < 2; f++)
#pragma unroll
            for (int i = 0; i < 4; i++) sa[f][i] = hscale_dn10(a[f][i]);

#pragma unroll
        for (int nc = 0; nc < 8; nc++) {
            uint4 w = wp[(ks * 8 + nc) * 32];
#pragma unroll
            for (int f = 0; f < 2; f++) {
                mma_f16(acc[f][nc], sa[f][0], sa[f][1], sa[f][2], sa[f][3],
                        w.y, w.w);
                mma_f16(acc[f][nc], a[f][0], a[f][1], a[f][2], a[f][3],
                        w.x, w.z);
            }
        }
    }

#pragma unroll
    for (int f = 0; f < 2; f++) {
        int r0 = m0 + wid * 32 + f * 16 + g;
        int r1 = r0 + 8;
#pragma unroll
        for (int nc = 0; nc < 8; nc++) {
            int col = n0 + nc * 8 + tg * 2;
            float2 bv = *(const float2*)(bias + col);
            *(float2*)(C + (size_t)r0 * 256 + col) =
                make_float2(acc[f][nc][0] + bv.x, acc[f][nc][1] + bv.y);
            *(float2*)(C + (size_t)r1 * 256 + col) =
                make_float2(acc[f][nc][2] + bv.x, acc[f][nc][3] + bv.y);
        }
    }
}

// ---------------------------------------------------------------------------
// Flash attention: 256 threads (8 warps, 256 queries/block), double-buffered
// K/V tiles (LDG for tile t+1 in flight during compute of tile t).
// grid = (SEQ/256, B*H). Warp: 32 queries (2 m16 frags).
// ---------------------------------------------------------------------------
__global__ __launch_bounds__(256) void flash_mma(const __half* __restrict__ Q,
                                                 const __half* __restrict__ K,
                                                 const __half* __restrict__ V,
                                                 const int* __restrict__ cntp,
                                                 __half* __restrict__ O) {
    __shared__ uint32_t Ks32[2][64 * 16];  // [buf][key][dim-pair-permuted]
    __shared__ __half Vd[2][32 * 80];      // [buf][dim][key-permuted]

    const int tid = threadIdx.x;
    const int lane = tid & 31;
    const int wid = tid >> 5;          // 0..7
    const int g = lane >> 2;
    const int tg = lane & 3;

    const int qt = blockIdx.x;         // 256-query tile
    const int b = blockIdx.y >> 3;
    const int h = blockIdx.y & 7;

    const int cnt = __ldg(cntp);
    const int nt = (cnt + 63) >> 6;

    // Q fragments fp16 (pre-scaled), direct uint32 loads
    uint32_t qf[2][2][4];
#pragma unroll
    for (int f = 0; f < 2; f++) {
        const __half* qb = Q +
            (size_t)(b * SEQ + qt * 256 + wid * 32 + f * 16) * D_MODEL + h * HEAD_DIM;
#pragma unroll
        for (int kc = 0; kc < 2; kc++) {
            qf[f][kc][0] = *(const uint32_t*)(qb + (size_t)g * D_MODEL + kc * 16 + 2 * tg);
            qf[f][kc][1] = *(const uint32_t*)(qb + (size_t)(g + 8) * D_MODEL + kc * 16 + 2 * tg);
            qf[f][kc][2] = *(const uint32_t*)(qb + (size_t)g * D_MODEL + kc * 16 + 8 + 2 * tg);
            qf[f][kc][3] = *(const uint32_t*)(qb + (size_t)(g + 8) * D_MODEL + kc * 16 + 8 + 2 * tg);
        }
    }

    float o[2][4][4];
#pragma unroll
    for (int f = 0; f < 2; f++)
#pragma unroll
        for (int i = 0; i < 4; i++)
#pragma unroll
            for (int j = 0; j < 4; j++) o[f][i][j] = 0.f;
    float lr[2][2] = {{0.f, 0.f}, {0.f, 0.f}};

    const __half* kbase = K + (size_t)b * SEQ * D_MODEL + h * HEAD_DIM;
    const __half* vbase = V + (size_t)b * SEQ * D_MODEL + h * HEAD_DIM;

    // Tile-invariant fill addressing: thread owns items tid, tid+256.
    int rI[2], koffA[2], koffB[2], voff[2];
    const __half* kptr[2];
    const __half* vptr[2];
#pragma unroll
    for (int i = 0; i < 2; i++) {
        int item = tid + i * 256;       // 0..511
        int r = item >> 3, pe = item & 7;
        rI[i] = r;
        int p0 = pe * 2, p1 = p0 + 1;
        koffA[i] = r * 16 + (p0 & 3) * 4 + (p0 >> 2);
        koffB[i] = r * 16 + (p1 & 3) * 4 + (p1 >> 2);
        int grp = r >> 4, u = r & 15, kp = u >> 1, odd = u & 1;
        int phi = grp * 16 + ((kp & 3) * 2 + (kp >> 2)) * 2 + odd;
        voff[i] = (pe * 4) * 80 + phi;
        kptr[i] = kbase + (size_t)r * D_MODEL + pe * 4;
        vptr[i] = vbase + (size_t)r * D_MODEL + pe * 4;
    }

    uint2 kreg[2], vreg[2];
    // prologue: load tile 0
#pragma unroll
    for (int i = 0; i < 2; i++) {
        kreg[i] = make_uint2(0u, 0u);
        vreg[i] = make_uint2(0u, 0u);
        if (rI[i] < cnt) {
            kreg[i] = *(const uint2*)kptr[i];
            vreg[i] = *(const uint2*)vptr[i];
        }
    }

    for (int t = 0; t < nt; t++) {
        const int bsel = t & 1;
        // store staged regs to smem
#pragma unroll
        for (int i = 0; i < 2; i++) {
            Ks32[bsel][koffA[i]] = kreg[i].x;
            Ks32[bsel][koffB[i]] = kreg[i].y;
            __half2 va = *(__half2*)&vreg[i].x;
            __half2 vb2 = *(__half2*)&vreg[i].y;
            Vd[bsel][voff[i]] = va.x;
            Vd[bsel][voff[i] + 80] = va.y;
            Vd[bsel][voff[i] + 160] = vb2.x;
            Vd[bsel][voff[i] + 240] = vb2.y;
        }
        // issue next tile's loads (in flight during compute)
        if (t + 1 < nt) {
            int keyoff = (t + 1) * 64;
#pragma unroll
            for (int i = 0; i < 2; i++) {
                kreg[i] = make_uint2(0u, 0u);
                vreg[i] = make_uint2(0u, 0u);
                if (keyoff + rI[i] < cnt) {
                    kreg[i] = *(const uint2*)(kptr[i] + (size_t)keyoff * D_MODEL);
                    vreg[i] = *(const uint2*)(vptr[i] + (size_t)keyoff * D_MODEL);
                }
            }
        }
        __syncthreads();

        const bool fix = (t == nt - 1) && (cnt & 63);
#pragma unroll
        for (int pc = 0; pc < 4; pc++) {
            uint4 kf0 = *(const uint4*)&Ks32[bsel][(pc * 16 + g) * 16 + 4 * tg];
            uint4 kf1 = *(const uint4*)&Ks32[bsel][(pc * 16 + 8 + g) * 16 + 4 * tg];

            uint32_t ph[2][4];
#pragma unroll
            for (int f = 0; f < 2; f++) {
                float s0[4] = {0.f, 0.f, 0.f, 0.f};
                float s1[4] = {0.f, 0.f, 0.f, 0.f};
                mma_f16(s0, qf[f][0][0], qf[f][0][1], qf[f][0][2], qf[f][0][3],
                        kf0.x, kf0.y);
                mma_f16(s0, qf[f][1][0], qf[f][1][1], qf[f][1][2], qf[f][1][3],
                        kf0.z, kf0.w);
                mma_f16(s1, qf[f][0][0], qf[f][0][1], qf[f][0][2], qf[f][0][3],
                        kf1.x, kf1.y);
                mma_f16(s1, qf[f][1][0], qf[f][1][1], qf[f][1][2], qf[f][1][3],
                        kf1.z, kf1.w);
                if (fix) {
                    int key0 = t * 64 + pc * 16 + 2 * tg;
                    if (key0 >= cnt) { s0[0] = -1e30f; s0[2] = -1e30f; }
                    if (key0 + 1 >= cnt) { s0[1] = -1e30f; s0[3] = -1e30f; }
                    int key1 = key0 + 8;
                    if (key1 >= cnt) { s1[0] = -1e30f; s1[2] = -1e30f; }
                    if (key1 + 1 >= cnt) { s1[1] = -1e30f; s1[3] = -1e30f; }
                }
                float e00 = ex2(s0[0]), e01 = ex2(s0[1]);
                float e02 = ex2(s0[2]), e03 = ex2(s0[3]);
                float e10 = ex2(s1[0]), e11 = ex2(s1[1]);
                float e12 = ex2(s1[2]), e13 = ex2(s1[3]);
                lr[f][0] += e00 + e01 + e10 + e11;
                lr[f][1] += e02 + e03 + e12 + e13;
                ph[f][0] = pack_f16(e00, e01);
                ph[f][1] = pack_f16(e02, e03);
                ph[f][2] = pack_f16(e10, e11);
                ph[f][3] = pack_f16(e12, e13);
            }

#pragma unroll
            for (int nc2 = 0; nc2 < 4; nc2++) {
                uint2 vb = *(const uint2*)&Vd[bsel][(nc2 * 8 + g) * 80 + pc * 16 + 4 * tg];
                mma_f16(o[0][nc2], ph[0][0], ph[0][1], ph[0][2], ph[0][3],
                        vb.x, vb.y);
                mma_f16(o[1][nc2], ph[1][0], ph[1][1], ph[1][2], ph[1][3],
                        vb.x, vb.y);
            }
        }
    }

#pragma unroll
    for (int f = 0; f < 2; f++) {
        float l0 = lr[f][0], l1 = lr[f][1];
        l0 += __shfl_xor_sync(0xffffffffu, l0, 1);
        l0 += __shfl_xor_sync(0xffffffffu, l0, 2);
        l1 += __shfl_xor_sync(0xffffffffu, l1, 1);
        l1 += __shfl_xor_sync(0xffffffffu, l1, 2);
        const float inv0 = 1.f / l0;
        const float inv1 = 1.f / l1;
        __half* ob = O +
            (size_t)(b * SEQ + qt * 256 + wid * 32 + f * 16) * D_MODEL + h * HEAD_DIM;
#pragma unroll
        for (int nc2 = 0; nc2 < 4; nc2++) {
            int col = nc2 * 8 + tg * 2;
            *(uint32_t*)(ob + (size_t)g * D_MODEL + col) =
                pack_f16(o[f][nc2][0] * inv0, o[f][nc2][1] * inv0);
            *(uint32_t*)(ob + (size_t)(g + 8) * D_MODEL + col) =
                pack_f16(o[f][nc2][2] * inv1, o[f][nc2][3] * inv1);
        }
    }
}

// ---------------------------------------------------------------------------
extern "C" void kernel_launch(void* const* d_in, const int* in_sizes, int n_in,
                              void* d_out, int out_size) {
    const float* q  = (const float*)d_in[0];
    const float* k  = (const float*)d_in[1];
    const float* v  = (const float*)d_in[2];
    const float* m  = (const float*)d_in[3];
    const float* wq = (const float*)d_in[4];
    const float* bq = (const float*)d_in[5];
    const float* wk = (const float*)d_in[6];
    const float* bk = (const float*)d_in[7];
    const float* wv = (const float*)d_in[8];
    const float* bv = (const float*)d_in[9];
    const float* wo = (const float*)d_in[10];
    const float* bo = (const float*)d_in[11];
    float* out = (float*)d_out;

    __half *gQ, *gK, *gV, *gO;
    int *gPos, *gCnt;
    uint4* gWp;
    cudaGetSymbolAddress((void**)&gQ, g_Qh);
    cudaGetSymbolAddress((void**)&gK, g_Kh);
    cudaGetSymbolAddress((void**)&gV, g_Vh);
    cudaGetSymbolAddress((void**)&gO, g_Oh);
    cudaGetSymbolAddress((void**)&gPos, g_pos);
    cudaGetSymbolAddress((void**)&gCnt, g_cnt);
    cudaGetSymbolAddress((void**)&gWp, g_Wp);

    scan_mask<<<1, 256>>>(m, gPos, gCnt);
    prep_w<<<512, 256>>>(wq, wk, wv, wo, gWp);

    const float qscale = 0.17677669529663687f * 1.4426950408889634f;
    dim3 qkv_grid(D_MODEL / 64, M_TOTAL / 128, 3);  // (4, 128, 3)
    gemm_qkv<<<qkv_grid, 128>>>(q, k, v, gWp, bq, bk, bv, gQ, gK, gV, gPos,
                                qscale);

    dim3 attn_grid(SEQ / 256, BATCH * N_HEADS);   // (8, 64)
    flash_mma<<<attn_grid, 256>>>(gQ, gK, gV, gCnt, gO);

    dim3 out_grid(D_MODEL / 64, M_TOTAL / 128);   // (4, 128)
    gemm_out<<<out_grid, 128>>>(gO, gWp + 3 * WP_MAT_STRIDE, bo, out);
}

// round 15
// speedup vs baseline: 1.0776x; 1.0776x over previous
#include <cuda_runtime.h>
#include <cuda_fp16.h>
#include <math.h>
#include <stdint.h>

#define D_MODEL 256
#define N_HEADS 8
#define HEAD_DIM 32
#define BATCH 8
#define SEQ 2048
#define M_TOTAL (BATCH * SEQ)  // 16384

// Scratch (alloc-free rule: __device__ globals)
__device__ __half g_Qh[M_TOTAL * D_MODEL];
__device__ __half g_Kh[M_TOTAL * D_MODEL];   // compacted keys
__device__ __half g_Vh[M_TOTAL * D_MODEL];   // compacted values
__device__ __half g_Oh[M_TOTAL * D_MODEL];
__device__ int g_pos[SEQ];
__device__ int g_cnt[1];
// Precomputed W fragments: [mat][nb][ks][nc][lane], uint4 = (hi[p0],lo[p0],hi[p0+4],lo[p0+4])
__device__ uint4 g_Wp[4 * 4 * 16 * 8 * 32];
#define WP_MAT_STRIDE (4 * 16 * 8 * 32)

// ---------------------------------------------------------------------------
// helpers
// ---------------------------------------------------------------------------
__device__ __forceinline__ void mma_f16(float* c, uint32_t a0, uint32_t a1,
                                        uint32_t a2, uint32_t a3,
                                        uint32_t b0, uint32_t b1) {
    asm volatile(
        "mma.sync.aligned.m16n8k16.row.col.f32.f16.f16.f32 "
        "{%0,%1,%2,%3}, {%4,%5,%6,%7}, {%8,%9}, {%0,%1,%2,%3};"
        : "+f"(c[0]), "+f"(c[1]), "+f"(c[2]), "+f"(c[3])
        : "r"(a0), "r"(a1), "r"(a2), "r"(a3), "r"(b0), "r"(b1));
}

__device__ __forceinline__ uint32_t pack_f16(float lo, float hi) {
    uint32_t r;
    asm("cvt.rn.f16x2.f32 %0, %1, %2;" : "=r"(r) : "f"(hi), "f"(lo));
    return r;
}

__device__ __forceinline__ float ex2(float x) {
    float r;
    asm("ex2.approx.ftz.f32 %0, %1;" : "=f"(r) : "f"(x));
    return r;
}

// multiply fp16x2 by 2^-10
__device__ __forceinline__ uint32_t hscale_dn10(uint32_t x) {
    uint32_t r;
    asm("mul.rn.f16x2 %0, %1, %2;" : "=r"(r) : "r"(x), "r"(0x14001400u));
    return r;
}

// ---------------------------------------------------------------------------
// prep_w + mask scan fused. Blocks 0..511: weight fragment prep.
// Block 512: mask scan (pos/cnt).
// ---------------------------------------------------------------------------
__global__ __launch_bounds__(256) void prep_w(const float* __restrict__ wq,
                                              const float* __restrict__ wk,
                                              const float* __restrict__ wv,
                                              const float* __restrict__ wo,
                                              uint4* __restrict__ Wp,
                                              const float* __restrict__ m,
                                              int* __restrict__ pos,
                                              int* __restrict__ cnt) {
    if (blockIdx.x == 512) {
        // ---- mask scan ----
        __shared__ int warpsum[8];
        const int tid = threadIdx.x;
        int keep[8], local[8], s = 0;
#pragma unroll
        for (int i = 0; i < 8; i++) {
            keep[i] = (m[tid * 8 + i] == 0.0f) ? 1 : 0;
            local[i] = s;
            s += keep[i];
        }
        const int lane = tid & 31, w = tid >> 5;
        int x = s;
#pragma unroll
        for (int d = 1; d < 32; d <<= 1) {
            int y = __shfl_up_sync(0xffffffffu, x, d);
            if (lane >= d) x += y;
        }
        if (lane == 31) warpsum[w] = x;
        __syncthreads();
        if (tid == 0) {
            int a = 0;
#pragma unroll
            for (int i = 0; i < 8; i++) {
                int t = warpsum[i];
                warpsum[i] = a;
                a += t;
            }
            *cnt = a;
        }
        __syncthreads();
        const int off = warpsum[w] + x - s;
#pragma unroll
        for (int i = 0; i < 8; i++)
            pos[tid * 8 + i] = keep[i] ? off + local[i] : -1;
        return;
    }

    // ---- weight prep ----
    int idx = blockIdx.x * 256 + threadIdx.x;  // 0..131071
    int mat = idx >> 15;
    int rem = idx & 32767;
    int p = rem >> 8;    // k-pair 0..127
    int n = rem & 255;   // column
    const float* W = (mat == 0) ? wq : (mat == 1) ? wk : (mat == 2) ? wv : wo;
    float w0 = W[(size_t)(2 * p) * 256 + n];
    float w1 = W[(size_t)(2 * p + 1) * 256 + n];
    uint32_t hip = pack_f16(w0, w1);
    __half2 hh = *(__half2*)&hip;
    uint32_t lop = pack_f16((w0 - __half2float(hh.x)) * 1024.0f,
                            (w1 - __half2float(hh.y)) * 1024.0f);
    int ks = p >> 3, q = p & 7;
    int tg = q & 3, sel = q >> 2;
    int nb = n >> 6, nc = (n >> 3) & 7, g = n & 7;
    int lanew = 4 * g + tg;
    uint2* dst = (uint2*)&Wp[(((mat * 4 + nb) * 16 + ks) * 8 + nc) * 32 + lanew];
    dst[sel] = make_uint2(hip, lop);
}

// ---------------------------------------------------------------------------
// Fused QKV projection GEMM, smem-free (R13-measured). blockIdx.z = matrix.
// ---------------------------------------------------------------------------
__global__ __launch_bounds__(128) void gemm_qkv(
    const float* __restrict__ q, const float* __restrict__ k,
    const float* __restrict__ v, const uint4* __restrict__ Wp,
    const float* __restrict__ bq, const float* __restrict__ bk,
    const float* __restrict__ bv, __half* __restrict__ Cq,
    __half* __restrict__ Ck, __half* __restrict__ Cv,
    const int* __restrict__ remap_kv, float qscale) {
    const int mat = blockIdx.z;
    const float* A = (mat == 0) ? q : (mat == 1) ? k : v;
    const float* bias = (mat == 0) ? bq : (mat == 1) ? bk : bv;
    __half* C = (mat == 0) ? Cq : (mat == 1) ? Ck : Cv;
    const int* remap = (mat == 0) ? (const int*)nullptr : remap_kv;
    const float alpha = (mat == 0) ? qscale : 1.0f;

    const int tid = threadIdx.x;
    const int lane = tid & 31;
    const int wid = tid >> 5;
    const int g = lane >> 2;
    const int tg = lane & 3;
    const int m0 = blockIdx.y * 128;
    const int n0 = blockIdx.x * 64;

    const uint4* wp = Wp + (size_t)mat * WP_MAT_STRIDE +
                      (size_t)blockIdx.x * (16 * 8 * 32) + lane;
    const float* ap0 = A + (size_t)(m0 + wid * 32 + g) * 256 + 2 * tg;
    const float* ap1 = ap0 + 8 * 256;
    const float* ap2 = ap0 + 16 * 256;
    const float* ap3 = ap0 + 24 * 256;

    float acc[2][8][4];
#pragma unroll
    for (int f = 0; f < 2; f++)
#pragma unroll
        for (int nc = 0; nc < 8; nc++)
#pragma unroll
            for (int i = 0; i < 4; i++) acc[f][nc][i] = 0.f;

#pragma unroll 4
    for (int ks = 0; ks < 16; ks++) {
        uint32_t a[2][4], sa[2][4];
        {
            float2 x0 = *(const float2*)(ap0 + ks * 16);
            float2 x1 = *(const float2*)(ap1 + ks * 16);
            float2 x2 = *(const float2*)(ap0 + ks * 16 + 8);
            float2 x3 = *(const float2*)(ap1 + ks * 16 + 8);
            a[0][0] = pack_f16(x0.x, x0.y);
            a[0][1] = pack_f16(x1.x, x1.y);
            a[0][2] = pack_f16(x2.x, x2.y);
            a[0][3] = pack_f16(x3.x, x3.y);
            float2 y0 = *(const float2*)(ap2 + ks * 16);
            float2 y1 = *(const float2*)(ap3 + ks * 16);
            float2 y2 = *(const float2*)(ap2 + ks * 16 + 8);
            float2 y3 = *(const float2*)(ap3 + ks * 16 + 8);
            a[1][0] = pack_f16(y0.x, y0.y);
            a[1][1] = pack_f16(y1.x, y1.y);
            a[1][2] = pack_f16(y2.x, y2.y);
            a[1][3] = pack_f16(y3.x, y3.y);
        }
#pragma unroll
        for (int f = 0; f < 2; f++)
#pragma unroll
            for (int i = 0; i < 4; i++) sa[f][i] = hscale_dn10(a[f][i]);

#pragma unroll
        for (int nc = 0; nc < 8; nc++) {
            uint4 w = wp[(ks * 8 + nc) * 32];
#pragma unroll
            for (int f = 0; f < 2; f++) {
                mma_f16(acc[f][nc], sa[f][0], sa[f][1], sa[f][2], sa[f][3],
                        w.y, w.w);
                mma_f16(acc[f][nc], a[f][0], a[f][1], a[f][2], a[f][3],
                        w.x, w.z);
            }
        }
    }

#pragma unroll
    for (int f = 0; f < 2; f++) {
        int r0 = m0 + wid * 32 + f * 16 + g;
        int r1 = r0 + 8;
        int d0 = r0, d1 = r1;
        bool st0 = true, st1 = true;
        if (remap) {
            int p0 = __ldg(remap + (r0 & (SEQ - 1)));
            int p1 = __ldg(remap + (r1 & (SEQ - 1)));
            st0 = p0 >= 0;
            st1 = p1 >= 0;
            d0 = (r0 & ~(SEQ - 1)) + p0;
            d1 = (r1 & ~(SEQ - 1)) + p1;
        }
#pragma unroll
        for (int nc = 0; nc < 8; nc++) {
            int col = n0 + nc * 8 + tg * 2;
            float2 bv2 = *(const float2*)(bias + col);
            if (st0)
                *(uint32_t*)(C + (size_t)d0 * 256 + col) =
                    pack_f16((acc[f][nc][0] + bv2.x) * alpha,
                             (acc[f][nc][1] + bv2.y) * alpha);
            if (st1)
                *(uint32_t*)(C + (size_t)d1 * 256 + col) =
                    pack_f16((acc[f][nc][2] + bv2.x) * alpha,
                             (acc[f][nc][3] + bv2.y) * alpha);
        }
    }
}

// ---------------------------------------------------------------------------
// Output projection GEMM, smem-free, 64-row block tile (2x blocks in flight):
// A fp16 direct loads -> C fp32. Warp = 16 rows (one m16 frag).
// ---------------------------------------------------------------------------
__global__ __launch_bounds__(128) void gemm_out(const __half* __restrict__ A,
                                                const uint4* __restrict__ Wp,
                                                const float* __restrict__ bias,
                                                float* __restrict__ C) {
    const int tid = threadIdx.x;
    const int lane = tid & 31;
    const int wid = tid >> 5;
    const int g = lane >> 2;
    const int tg = lane & 3;
    const int m0 = blockIdx.y * 64;
    const int n0 = blockIdx.x * 64;

    const uint4* wp = Wp + (size_t)blockIdx.x * (16 * 8 * 32) + lane;
    const __half* ap0 = A + (size_t)(m0 + wid * 16 + g) * 256 + 2 * tg;
    const __half* ap1 = ap0 + 8 * 256;

    float acc[8][4];
#pragma unroll
    for (int nc = 0; nc < 8; nc++)
#pragma unroll
        for (int i = 0; i < 4; i++) acc[nc][i] = 0.f;

#pragma unroll 4
    for (int ks = 0; ks < 16; ks++) {
        uint32_t a[4], sa[4];
        a[0] = *(const uint32_t*)(ap0 + ks * 16);
        a[1] = *(const uint32_t*)(ap1 + ks * 16);
        a[2] = *(const uint32_t*)(ap0 + ks * 16 + 8);
        a[3] = *(const uint32_t*)(ap1 + ks * 16 + 8);
#pragma unroll
        for (int i = 0; i < 4; i++) sa[i] = hscale_dn10(a[i]);

#pragma unroll
        for (int nc = 0; nc < 8; nc++) {
            uint4 w = wp[(ks * 8 + nc) * 32];
            mma_f16(acc[nc], sa[0], sa[1], sa[2], sa[3], w.y, w.w);
            mma_f16(acc[nc], a[0], a[1], a[2], a[3], w.x, w.z);
        }
    }

    int r0 = m0 + wid * 16 + g;
    int r1 = r0 + 8;
#pragma unroll
    for (int nc = 0; nc < 8; nc++) {
        int col = n0 + nc * 8 + tg * 2;
        float2 bv = *(const float2*)(bias + col);
        *(float2*)(C + (size_t)r0 * 256 + col) =
            make_float2(acc[nc][0] + bv.x, acc[nc][1] + bv.y);
        *(float2*)(C + (size_t)r1 * 256 + col) =
            make_float2(acc[nc][2] + bv.x, acc[nc][3] + bv.y);
    }
}

// ---------------------------------------------------------------------------
// Flash attention (R13-measured 88us, byte-identical).
// grid = (SEQ/128, B*H), block = 128 (4 warps). Warp: 32 queries.
// ---------------------------------------------------------------------------
__global__ __launch_bounds__(128) void flash_mma(const __half* __restrict__ Q,
                                                 const __half* __restrict__ K,
                                                 const __half* __restrict__ V,
                                                 const int* __restrict__ cntp,
                                                 __half* __restrict__ O) {
    __shared__ uint32_t Ks32[64 * 16];  // [key][dim-pair-permuted]
    __shared__ __half Vd[32 * 80];      // [dim][key-permuted], stride 80

    const int tid = threadIdx.x;
    const int lane = tid & 31;
    const int wid = tid >> 5;
    const int g = lane >> 2;
    const int tg = lane & 3;

    const int qt = blockIdx.x;
    const int b = blockIdx.y >> 3;
    const int h = blockIdx.y & 7;

    const int cnt = __ldg(cntp);
    const int nt = (cnt + 63) >> 6;

    uint32_t qf[2][2][4];
#pragma unroll
    for (int f = 0; f < 2; f++) {
        const __half* qb = Q +
            (size_t)(b * SEQ + qt * 128 + wid * 32 + f * 16) * D_MODEL + h * HEAD_DIM;
#pragma unroll
        for (int kc = 0; kc < 2; kc++) {
            qf[f][kc][0] = *(const uint32_t*)(qb + (size_t)g * D_MODEL + kc * 16 + 2 * tg);
            qf[f][kc][1] = *(const uint32_t*)(qb + (size_t)(g + 8) * D_MODEL + kc * 16 + 2 * tg);
            qf[f][kc][2] = *(const uint32_t*)(qb + (size_t)g * D_MODEL + kc * 16 + 8 + 2 * tg);
            qf[f][kc][3] = *(const uint32_t*)(qb + (size_t)(g + 8) * D_MODEL + kc * 16 + 8 + 2 * tg);
        }
    }

    float o[2][4][4];
#pragma unroll
    for (int f = 0; f < 2; f++)
#pragma unroll
        for (int i = 0; i < 4; i++)
#pragma unroll
            for (int j = 0; j < 4; j++) o[f][i][j] = 0.f;
    float lr[2][2] = {{0.f, 0.f}, {0.f, 0.f}};

    const __half* kbase = K + (size_t)b * SEQ * D_MODEL + h * HEAD_DIM;
    const __half* vbase = V + (size_t)b * SEQ * D_MODEL + h * HEAD_DIM;

    for (int t = 0; t < nt; t++) {
        __syncthreads();
#pragma unroll
        for (int i = 0; i < 4; i++) {
            int item = tid + i * 128;
            int r = item >> 3, pe = item & 7;
            int key = t * 64 + r;
            uint2 kv2 = make_uint2(0u, 0u), vv2 = make_uint2(0u, 0u);
            if (key < cnt) {
                kv2 = *(const uint2*)(kbase + (size_t)key * D_MODEL + pe * 4);
                vv2 = *(const uint2*)(vbase + (size_t)key * D_MODEL + pe * 4);
            }
            int p0 = pe * 2;
            Ks32[r * 16 + (p0 & 3) * 4 + (p0 >> 2)] = kv2.x;
            int p1 = p0 + 1;
            Ks32[r * 16 + (p1 & 3) * 4 + (p1 >> 2)] = kv2.y;
            int grp = r >> 4, u = r & 15, kp = u >> 1, odd = u & 1;
            int phi = grp * 16 + ((kp & 3) * 2 + (kp >> 2)) * 2 + odd;
            __half2 va = *(__half2*)&vv2.x;
            __half2 vb2 = *(__half2*)&vv2.y;
            int d0 = pe * 4;
            Vd[(d0 + 0) * 80 + phi] = va.x;
            Vd[(d0 + 1) * 80 + phi] = va.y;
            Vd[(d0 + 2) * 80 + phi] = vb2.x;
            Vd[(d0 + 3) * 80 + phi] = vb2.y;
        }
        __syncthreads();

        const bool fix = (t == nt - 1) && (cnt & 63);
#pragma unroll
        for (int pc = 0; pc < 4; pc++) {
            uint4 kf0 = *(const uint4*)&Ks32[(pc * 16 + g) * 16 + 4 * tg];
            uint4 kf1 = *(const uint4*)&Ks32[(pc * 16 + 8 + g) * 16 + 4 * tg];

            uint32_t ph[2][4];
#pragma unroll
            for (int f = 0; f < 2; f++) {
                float s0[4] = {0.f, 0.f, 0.f, 0.f};
                float s1[4] = {0.f, 0.f, 0.f, 0.f};
                mma_f16(s0, qf[f][0][0], qf[f][0][1], qf[f][0][2], qf[f][0][3],
                        kf0.x, kf0.y);
                mma_f16(s0, qf[f][1][0], qf[f][1][1], qf[f][1][2], qf[f][1][3],
                        kf0.z, kf0.w);
                mma_f16(s1, qf[f][0][0], qf[f][0][1], qf[f][0][2], qf[f][0][3],
                        kf1.x, kf1.y);
                mma_f16(s1, qf[f][1][0], qf[f][1][1], qf[f][1][2], qf[f][1][3],
                        kf1.z, kf1.w);
                if (fix) {
                    int key0 = t * 64 + pc * 16 + 2 * tg;
                    if (key0 >= cnt) { s0[0] = -1e30f; s0[2] = -1e30f; }
                    if (key0 + 1 >= cnt) { s0[1] = -1e30f; s0[3] = -1e30f; }
                    int key1 = key0 + 8;
                    if (key1 >= cnt) { s1[0] = -1e30f; s1[2] = -1e30f; }
                    if (key1 + 1 >= cnt) { s1[1] = -1e30f; s1[3] = -1e30f; }
                }
                float e00 = ex2(s0[0]), e01 = ex2(s0[1]);
                float e02 = ex2(s0[2]), e03 = ex2(s0[3]);
                float e10 = ex2(s1[0]), e11 = ex2(s1[1]);
                float e12 = ex2(s1[2]), e13 = ex2(s1[3]);
                lr[f][0] += e00 + e01 + e10 + e11;
                lr[f][1] += e02 + e03 + e12 + e13;
                ph[f][0] = pack_f16(e00, e01);
                ph[f][1] = pack_f16(e02, e03);
                ph[f][2] = pack_f16(e10, e11);
                ph[f][3] = pack_f16(e12, e13);
            }

#pragma unroll
            for (int nc2 = 0; nc2 < 4; nc2++) {
                uint2 vb = *(const uint2*)&Vd[(nc2 * 8 + g) * 80 + pc * 16 + 4 * tg];
                mma_f16(o[0][nc2], ph[0][0], ph[0][1], ph[0][2], ph[0][3],
                        vb.x, vb.y);
                mma_f16(o[1][nc2], ph[1][0], ph[1][1], ph[1][2], ph[1][3],
                        vb.x, vb.y);
            }
        }
    }

#pragma unroll
    for (int f = 0; f < 2; f++) {
        float l0 = lr[f][0], l1 = lr[f][1];
        l0 += __shfl_xor_sync(0xffffffffu, l0, 1);
        l0 += __shfl_xor_sync(0xffffffffu, l0, 2);
        l1 += __shfl_xor_sync(0xffffffffu, l1, 1);
        l1 += __shfl_xor_sync(0xffffffffu, l1, 2);
        const float inv0 = 1.f / l0;
        const float inv1 = 1.f / l1;
        __half* ob = O +
            (size_t)(b * SEQ + qt * 128 + wid * 32 + f * 16) * D_MODEL + h * HEAD_DIM;
#pragma unroll
        for (int nc2 = 0; nc2 < 4; nc2++) {
            int col = nc2 * 8 + tg * 2;
            *(uint32_t*)(ob + (size_t)g * D_MODEL + col) =
                pack_f16(o[f][nc2][0] * inv0, o[f][nc2][1] * inv0);
            *(uint32_t*)(ob + (size_t)(g + 8) * D_MODEL + col) =
                pack_f16(o[f][nc2][2] * inv1, o[f][nc2][3] * inv1);
        }
    }
}

// ---------------------------------------------------------------------------
extern "C" void kernel_launch(void* const* d_in, const int* in_sizes, int n_in,
                              void* d_out, int out_size) {
    const float* q  = (const float*)d_in[0];
    const float* k  = (const float*)d_in[1];
    const float* v  = (const float*)d_in[2];
    const float* m  = (const float*)d_in[3];
    const float* wq = (const float*)d_in[4];
    const float* bq = (const float*)d_in[5];
    const float* wk = (const float*)d_in[6];
    const float* bk = (const float*)d_in[7];
    const float* wv = (const float*)d_in[8];
    const float* bv = (const float*)d_in[9];
    const float* wo = (const float*)d_in[10];
    const float* bo = (const float*)d_in[11];
    float* out = (float*)d_out;

    __half *gQ, *gK, *gV, *gO;
    int *gPos, *gCnt;
    uint4* gWp;
    cudaGetSymbolAddress((void**)&gQ, g_Qh);
    cudaGetSymbolAddress((void**)&gK, g_Kh);
    cudaGetSymbolAddress((void**)&gV, g_Vh);
    cudaGetSymbolAddress((void**)&gO, g_Oh);
    cudaGetSymbolAddress((void**)&gPos, g_pos);
    cudaGetSymbolAddress((void**)&gCnt, g_cnt);
    cudaGetSymbolAddress((void**)&gWp, g_Wp);

    prep_w<<<513, 256>>>(wq, wk, wv, wo, gWp, m, gPos, gCnt);

    const float qscale = 0.17677669529663687f * 1.4426950408889634f;
    dim3 qkv_grid(D_MODEL / 64, M_TOTAL / 128, 3);  // (4, 128, 3)
    gemm_qkv<<<qkv_grid, 128>>>(q, k, v, gWp, bq, bk, bv, gQ, gK, gV, gPos,
                                qscale);

    dim3 attn_grid(SEQ / 128, BATCH * N_HEADS);   // (16, 64)
    flash_mma<<<attn_grid, 128>>>(gQ, gK, gV, gCnt, gO);

    dim3 out_grid(D_MODEL / 64, M_TOTAL / 64);    // (4, 256)
    gemm_out<<<out_grid, 128>>>(gO, gWp + 3 * WP_MAT_STRIDE, bo, out);
}

// round 16
// speedup vs baseline: 1.1437x; 1.0613x over previous
#include <cuda_runtime.h>
#include <cuda_fp16.h>
#include <math.h>
#include <stdint.h>

#define D_MODEL 256
#define N_HEADS 8
#define HEAD_DIM 32
#define BATCH 8
#define SEQ 2048
#define M_TOTAL (BATCH * SEQ)  // 16384

// Scratch (alloc-free rule: __device__ globals)
__device__ __half g_Qh[M_TOTAL * D_MODEL];
__device__ __half g_Kh[M_TOTAL * D_MODEL];   // compacted keys
__device__ __half g_Vh[M_TOTAL * D_MODEL];   // compacted values
__device__ __half g_Oh[M_TOTAL * D_MODEL];
__device__ int g_pos[SEQ];
__device__ int g_cnt[1];
// Precomputed W fragments: [mat][nb][ks][nc][lane], uint4 = (hi[p0],lo[p0],hi[p0+4],lo[p0+4])
__device__ uint4 g_Wp[4 * 4 * 16 * 8 * 32];
#define WP_MAT_STRIDE (4 * 16 * 8 * 32)

#define V_STRIDE 144  // halves per dim row (72 words == 8 mod 32 -> clean banks)

// ---------------------------------------------------------------------------
// helpers
// ---------------------------------------------------------------------------
__device__ __forceinline__ void mma_f16(float* c, uint32_t a0, uint32_t a1,
                                        uint32_t a2, uint32_t a3,
                                        uint32_t b0, uint32_t b1) {
    asm volatile(
        "mma.sync.aligned.m16n8k16.row.col.f32.f16.f16.f32 "
        "{%0,%1,%2,%3}, {%4,%5,%6,%7}, {%8,%9}, {%0,%1,%2,%3};"
        : "+f"(c[0]), "+f"(c[1]), "+f"(c[2]), "+f"(c[3])
        : "r"(a0), "r"(a1), "r"(a2), "r"(a3), "r"(b0), "r"(b1));
}

__device__ __forceinline__ uint32_t pack_f16(float lo, float hi) {
    uint32_t r;
    asm("cvt.rn.f16x2.f32 %0, %1, %2;" : "=r"(r) : "f"(hi), "f"(lo));
    return r;
}

__device__ __forceinline__ float ex2(float x) {
    float r;
    asm("ex2.approx.ftz.f32 %0, %1;" : "=f"(r) : "f"(x));
    return r;
}

// multiply fp16x2 by 2^-10
__device__ __forceinline__ uint32_t hscale_dn10(uint32_t x) {
    uint32_t r;
    asm("mul.rn.f16x2 %0, %1, %2;" : "=r"(r) : "r"(x), "r"(0x14001400u));
    return r;
}

// ---------------------------------------------------------------------------
// prep_w + mask scan fused. Blocks 0..511: weight fragment prep.
// Block 512: mask scan (pos/cnt).
// ---------------------------------------------------------------------------
__global__ __launch_bounds__(256) void prep_w(const float* __restrict__ wq,
                                              const float* __restrict__ wk,
                                              const float* __restrict__ wv,
                                              const float* __restrict__ wo,
                                              uint4* __restrict__ Wp,
                                              const float* __restrict__ m,
                                              int* __restrict__ pos,
                                              int* __restrict__ cnt) {
    if (blockIdx.x == 512) {
        __shared__ int warpsum[8];
        const int tid = threadIdx.x;
        int keep[8], local[8], s = 0;
#pragma unroll
        for (int i = 0; i < 8; i++) {
            keep[i] = (m[tid * 8 + i] == 0.0f) ? 1 : 0;
            local[i] = s;
            s += keep[i];
        }
        const int lane = tid & 31, w = tid >> 5;
        int x = s;
#pragma unroll
        for (int d = 1; d < 32; d <<= 1) {
            int y = __shfl_up_sync(0xffffffffu, x, d);
            if (lane >= d) x += y;
        }
        if (lane == 31) warpsum[w] = x;
        __syncthreads();
        if (tid == 0) {
            int a = 0;
#pragma unroll
            for (int i = 0; i < 8; i++) {
                int t = warpsum[i];
                warpsum[i] = a;
                a += t;
            }
            *cnt = a;
        }
        __syncthreads();
        const int off = warpsum[w] + x - s;
#pragma unroll
        for (int i = 0; i < 8; i++)
            pos[tid * 8 + i] = keep[i] ? off + local[i] : -1;
        return;
    }

    int idx = blockIdx.x * 256 + threadIdx.x;  // 0..131071
    int mat = idx >> 15;
    int rem = idx & 32767;
    int p = rem >> 8;    // k-pair 0..127
    int n = rem & 255;   // column
    const float* W = (mat == 0) ? wq : (mat == 1) ? wk : (mat == 2) ? wv : wo;
    float w0 = W[(size_t)(2 * p) * 256 + n];
    float w1 = W[(size_t)(2 * p + 1) * 256 + n];
    uint32_t hip = pack_f16(w0, w1);
    __half2 hh = *(__half2*)&hip;
    uint32_t lop = pack_f16((w0 - __half2float(hh.x)) * 1024.0f,
                            (w1 - __half2float(hh.y)) * 1024.0f);
    int ks = p >> 3, q = p & 7;
    int tg = q & 3, sel = q >> 2;
    int nb = n >> 6, nc = (n >> 3) & 7, g = n & 7;
    int lanew = 4 * g + tg;
    uint2* dst = (uint2*)&Wp[(((mat * 4 + nb) * 16 + ks) * 8 + nc) * 32 + lanew];
    dst[sel] = make_uint2(hip, lop);
}

// ---------------------------------------------------------------------------
// Fused QKV projection GEMM, smem-free (R13-measured). blockIdx.z = matrix.
// ---------------------------------------------------------------------------
__global__ __launch_bounds__(128) void gemm_qkv(
    const float* __restrict__ q, const float* __restrict__ k,
    const float* __restrict__ v, const uint4* __restrict__ Wp,
    const float* __restrict__ bq, const float* __restrict__ bk,
    const float* __restrict__ bv, __half* __restrict__ Cq,
    __half* __restrict__ Ck, __half* __restrict__ Cv,
    const int* __restrict__ remap_kv, float qscale) {
    const int mat = blockIdx.z;
    const float* A = (mat == 0) ? q : (mat == 1) ? k : v;
    const float* bias = (mat == 0) ? bq : (mat == 1) ? bk : bv;
    __half* C = (mat == 0) ? Cq : (mat == 1) ? Ck : Cv;
    const int* remap = (mat == 0) ? (const int*)nullptr : remap_kv;
    const float alpha = (mat == 0) ? qscale : 1.0f;

    const int tid = threadIdx.x;
    const int lane = tid & 31;
    const int wid = tid >> 5;
    const int g = lane >> 2;
    const int tg = lane & 3;
    const int m0 = blockIdx.y * 128;
    const int n0 = blockIdx.x * 64;

    const uint4* wp = Wp + (size_t)mat * WP_MAT_STRIDE +
                      (size_t)blockIdx.x * (16 * 8 * 32) + lane;
    const float* ap0 = A + (size_t)(m0 + wid * 32 + g) * 256 + 2 * tg;
    const float* ap1 = ap0 + 8 * 256;
    const float* ap2 = ap0 + 16 * 256;
    const float* ap3 = ap0 + 24 * 256;

    float acc[2][8][4];
#pragma unroll
    for (int f = 0; f < 2; f++)
#pragma unroll
        for (int nc = 0; nc < 8; nc++)
#pragma unroll
            for (int i = 0; i < 4; i++) acc[f][nc][i] = 0.f;

#pragma unroll 4
    for (int ks = 0; ks < 16; ks++) {
        uint32_t a[2][4], sa[2][4];
        {
            float2 x0 = *(const float2*)(ap0 + ks * 16);
            float2 x1 = *(const float2*)(ap1 + ks * 16);
            float2 x2 = *(const float2*)(ap0 + ks * 16 + 8);
            float2 x3 = *(const float2*)(ap1 + ks * 16 + 8);
            a[0][0] = pack_f16(x0.x, x0.y);
            a[0][1] = pack_f16(x1.x, x1.y);
            a[0][2] = pack_f16(x2.x, x2.y);
            a[0][3] = pack_f16(x3.x, x3.y);
            float2 y0 = *(const float2*)(ap2 + ks * 16);
            float2 y1 = *(const float2*)(ap3 + ks * 16);
            float2 y2 = *(const float2*)(ap2 + ks * 16 + 8);
            float2 y3 = *(const float2*)(ap3 + ks * 16 + 8);
            a[1][0] = pack_f16(y0.x, y0.y);
            a[1][1] = pack_f16(y1.x, y1.y);
            a[1][2] = pack_f16(y2.x, y2.y);
            a[1][3] = pack_f16(y3.x, y3.y);
        }
#pragma unroll
        for (int f = 0; f < 2; f++)
#pragma unroll
            for (int i = 0; i < 4; i++) sa[f][i] = hscale_dn10(a[f][i]);

#pragma unroll
        for (int nc = 0; nc < 8; nc++) {
            uint4 w = wp[(ks * 8 + nc) * 32];
#pragma unroll
            for (int f = 0; f < 2; f++) {
                mma_f16(acc[f][nc], sa[f][0], sa[f][1], sa[f][2], sa[f][3],
                        w.y, w.w);
                mma_f16(acc[f][nc], a[f][0], a[f][1], a[f][2], a[f][3],
                        w.x, w.z);
            }
        }
    }

#pragma unroll
    for (int f = 0; f < 2; f++) {
        int r0 = m0 + wid * 32 + f * 16 + g;
        int r1 = r0 + 8;
        int d0 = r0, d1 = r1;
        bool st0 = true, st1 = true;
        if (remap) {
            int p0 = __ldg(remap + (r0 & (SEQ - 1)));
            int p1 = __ldg(remap + (r1 & (SEQ - 1)));
            st0 = p0 >= 0;
            st1 = p1 >= 0;
            d0 = (r0 & ~(SEQ - 1)) + p0;
            d1 = (r1 & ~(SEQ - 1)) + p1;
        }
#pragma unroll
        for (int nc = 0; nc < 8; nc++) {
            int col = n0 + nc * 8 + tg * 2;
            float2 bv2 = *(const float2*)(bias + col);
            if (st0)
                *(uint32_t*)(C + (size_t)d0 * 256 + col) =
                    pack_f16((acc[f][nc][0] + bv2.x) * alpha,
                             (acc[f][nc][1] + bv2.y) * alpha);
            if (st1)
                *(uint32_t*)(C + (size_t)d1 * 256 + col) =
                    pack_f16((acc[f][nc][2] + bv2.x) * alpha,
                             (acc[f][nc][3] + bv2.y) * alpha);
        }
    }
}

// ---------------------------------------------------------------------------
// Output projection GEMM (R13-measured, 128-row tile): A fp16 -> C fp32.
// ---------------------------------------------------------------------------
__global__ __launch_bounds__(128) void gemm_out(const __half* __restrict__ A,
                                                const uint4* __restrict__ Wp,
                                                const float* __restrict__ bias,
                                                float* __restrict__ C) {
    const int tid = threadIdx.x;
    const int lane = tid & 31;
    const int wid = tid >> 5;
    const int g = lane >> 2;
    const int tg = lane & 3;
    const int m0 = blockIdx.y * 128;
    const int n0 = blockIdx.x * 64;

    const uint4* wp = Wp + (size_t)blockIdx.x * (16 * 8 * 32) + lane;
    const __half* ap0 = A + (size_t)(m0 + wid * 32 + g) * 256 + 2 * tg;
    const __half* ap1 = ap0 + 8 * 256;
    const __half* ap2 = ap0 + 16 * 256;
    const __half* ap3 = ap0 + 24 * 256;

    float acc[2][8][4];
#pragma unroll
    for (int f = 0; f < 2; f++)
#pragma unroll
        for (int nc = 0; nc < 8; nc++)
#pragma unroll
            for (int i = 0; i < 4; i++) acc[f][nc][i] = 0.f;

#pragma unroll 4
    for (int ks = 0; ks < 16; ks++) {
        uint32_t a[2][4], sa[2][4];
        a[0][0] = *(const uint32_t*)(ap0 + ks * 16);
        a[0][1] = *(const uint32_t*)(ap1 + ks * 16);
        a[0][2] = *(const uint32_t*)(ap0 + ks * 16 + 8);
        a[0][3] = *(const uint32_t*)(ap1 + ks * 16 + 8);
        a[1][0] = *(const uint32_t*)(ap2 + ks * 16);
        a[1][1] = *(const uint32_t*)(ap3 + ks * 16);
        a[1][2] = *(const uint32_t*)(ap2 + ks * 16 + 8);
        a[1][3] = *(const uint32_t*)(ap3 + ks * 16 + 8);
#pragma unroll
        for (int f = 0; f < 2; f++)
#pragma unroll
            for (int i = 0; i < 4; i++) sa[f][i] = hscale_dn10(a[f][i]);

#pragma unroll
        for (int nc = 0; nc < 8; nc++) {
            uint4 w = wp[(ks * 8 + nc) * 32];
#pragma unroll
            for (int f = 0; f < 2; f++) {
                mma_f16(acc[f][nc], sa[f][0], sa[f][1], sa[f][2], sa[f][3],
                        w.y, w.w);
                mma_f16(acc[f][nc], a[f][0], a[f][1], a[f][2], a[f][3],
                        w.x, w.z);
            }
        }
    }

#pragma unroll
    for (int f = 0; f < 2; f++) {
        int r0 = m0 + wid * 32 + f * 16 + g;
        int r1 = r0 + 8;
#pragma unroll
        for (int nc = 0; nc < 8; nc++) {
            int col = n0 + nc * 8 + tg * 2;
            float2 bv = *(const float2*)(bias + col);
            *(float2*)(C + (size_t)r0 * 256 + col) =
                make_float2(acc[f][nc][0] + bv.x, acc[f][nc][1] + bv.y);
            *(float2*)(C + (size_t)r1 * 256 + col) =
                make_float2(acc[f][nc][2] + bv.x, acc[f][nc][3] + bv.y);
        }
    }
}

// ---------------------------------------------------------------------------
// Flash attention: 128-key tiles (half the syncs / LDG exposures of R13).
// grid = (SEQ/128, B*H), block = 128 (4 warps). Warp: 32 queries.
// ---------------------------------------------------------------------------
__global__ __launch_bounds__(128) void flash_mma(const __half* __restrict__ Q,
                                                 const __half* __restrict__ K,
                                                 const __half* __restrict__ V,
                                                 const int* __restrict__ cntp,
                                                 __half* __restrict__ O) {
    __shared__ uint32_t Ks32[128 * 16];     // [key][dim-pair-permuted]
    __shared__ __half Vd[32 * V_STRIDE];    // [dim][key-permuted]

    const int tid = threadIdx.x;
    const int lane = tid & 31;
    const int wid = tid >> 5;
    const int g = lane >> 2;
    const int tg = lane & 3;

    const int qt = blockIdx.x;
    const int b = blockIdx.y >> 3;
    const int h = blockIdx.y & 7;

    const int cnt = __ldg(cntp);
    const int nt = (cnt + 127) >> 7;

    uint32_t qf[2][2][4];
#pragma unroll
    for (int f = 0; f < 2; f++) {
        const __half* qb = Q +
            (size_t)(b * SEQ + qt * 128 + wid * 32 + f * 16) * D_MODEL + h * HEAD_DIM;
#pragma unroll
        for (int kc = 0; kc < 2; kc++) {
            qf[f][kc][0] = *(const uint32_t*)(qb + (size_t)g * D_MODEL + kc * 16 + 2 * tg);
            qf[f][kc][1] = *(const uint32_t*)(qb + (size_t)(g + 8) * D_MODEL + kc * 16 + 2 * tg);
            qf[f][kc][2] = *(const uint32_t*)(qb + (size_t)g * D_MODEL + kc * 16 + 8 + 2 * tg);
            qf[f][kc][3] = *(const uint32_t*)(qb + (size_t)(g + 8) * D_MODEL + kc * 16 + 8 + 2 * tg);
        }
    }

    float o[2][4][4];
#pragma unroll
    for (int f = 0; f < 2; f++)
#pragma unroll
        for (int i = 0; i < 4; i++)
#pragma unroll
            for (int j = 0; j < 4; j++) o[f][i][j] = 0.f;
    float lr[2][2] = {{0.f, 0.f}, {0.f, 0.f}};

    const __half* kbase = K + (size_t)b * SEQ * D_MODEL + h * HEAD_DIM;
    const __half* vbase = V + (size_t)b * SEQ * D_MODEL + h * HEAD_DIM;

    for (int t = 0; t < nt; t++) {
        __syncthreads();
#pragma unroll
        for (int i = 0; i < 8; i++) {
            int item = tid + i * 128;          // 0..1023
            int r = item >> 3, pe = item & 7;  // key row 0..127
            int key = t * 128 + r;
            uint2 kv2 = make_uint2(0u, 0u), vv2 = make_uint2(0u, 0u);
            if (key < cnt) {
                kv2 = *(const uint2*)(kbase + (size_t)key * D_MODEL + pe * 4);
                vv2 = *(const uint2*)(vbase + (size_t)key * D_MODEL + pe * 4);
            }
            int p0 = pe * 2;
            Ks32[r * 16 + (p0 & 3) * 4 + (p0 >> 2)] = kv2.x;
            int p1 = p0 + 1;
            Ks32[r * 16 + (p1 & 3) * 4 + (p1 >> 2)] = kv2.y;
            int grp = r >> 4, u = r & 15, kp = u >> 1, odd = u & 1;
            int phi = grp * 16 + ((kp & 3) * 2 + (kp >> 2)) * 2 + odd;
            __half2 va = *(__half2*)&vv2.x;
            __half2 vb2 = *(__half2*)&vv2.y;
            int d0 = pe * 4;
            Vd[(d0 + 0) * V_STRIDE + phi] = va.x;
            Vd[(d0 + 1) * V_STRIDE + phi] = va.y;
            Vd[(d0 + 2) * V_STRIDE + phi] = vb2.x;
            Vd[(d0 + 3) * V_STRIDE + phi] = vb2.y;
        }
        __syncthreads();

        const bool fix = (t == nt - 1) && (cnt & 127);
#pragma unroll
        for (int pc = 0; pc < 8; pc++) {
            uint4 kf0 = *(const uint4*)&Ks32[(pc * 16 + g) * 16 + 4 * tg];
            uint4 kf1 = *(const uint4*)&Ks32[(pc * 16 + 8 + g) * 16 + 4 * tg];

            uint32_t ph[2][4];
#pragma unroll
            for (int f = 0; f < 2; f++) {
                float s0[4] = {0.f, 0.f, 0.f, 0.f};
                float s1[4] = {0.f, 0.f, 0.f, 0.f};
                mma_f16(s0, qf[f][0][0], qf[f][0][1], qf[f][0][2], qf[f][0][3],
                        kf0.x, kf0.y);
                mma_f16(s0, qf[f][1][0], qf[f][1][1], qf[f][1][2], qf[f][1][3],
                        kf0.z, kf0.w);
                mma_f16(s1, qf[f][0][0], qf[f][0][1], qf[f][0][2], qf[f][0][3],
                        kf1.x, kf1.y);
                mma_f16(s1, qf[f][1][0], qf[f][1][1], qf[f][1][2], qf[f][1][3],
                        kf1.z, kf1.w);
                if (fix) {
                    int key0 = t * 128 + pc * 16 + 2 * tg;
                    if (key0 >= cnt) { s0[0] = -1e30f; s0[2] = -1e30f; }
                    if (key0 + 1 >= cnt) { s0[1] = -1e30f; s0[3] = -1e30f; }
                    int key1 = key0 + 8;
                    if (key1 >= cnt) { s1[0] = -1e30f; s1[2] = -1e30f; }
                    if (key1 + 1 >= cnt) { s1[1] = -1e30f; s1[3] = -1e30f; }
                }
                float e00 = ex2(s0[0]), e01 = ex2(s0[1]);
                float e02 = ex2(s0[2]), e03 = ex2(s0[3]);
                float e10 = ex2(s1[0]), e11 = ex2(s1[1]);
                float e12 = ex2(s1[2]), e13 = ex2(s1[3]);
                lr[f][0] += e00 + e01 + e10 + e11;
                lr[f][1] += e02 + e03 + e12 + e13;
                ph[f][0] = pack_f16(e00, e01);
                ph[f][1] = pack_f16(e02, e03);
                ph[f][2] = pack_f16(e10, e11);
                ph[f][3] = pack_f16(e12, e13);
            }

#pragma unroll
            for (int nc2 = 0; nc2 < 4; nc2++) {
                uint2 vb = *(const uint2*)&Vd[(nc2 * 8 + g) * V_STRIDE + pc * 16 + 4 * tg];
                mma_f16(o[0][nc2], ph[0][0], ph[0][1], ph[0][2], ph[0][3],
                        vb.x, vb.y);
                mma_f16(o[1][nc2], ph[1][0], ph[1][1], ph[1][2], ph[1][3],
                        vb.x, vb.y);
            }
        }
    }

#pragma unroll
    for (int f = 0; f < 2; f++) {
        float l0 = lr[f][0], l1 = lr[f][1];
        l0 += __shfl_xor_sync(0xffffffffu, l0, 1);
        l0 += __shfl_xor_sync(0xffffffffu, l0, 2);
        l1 += __shfl_xor_sync(0xffffffffu, l1, 1);
        l1 += __shfl_xor_sync(0xffffffffu, l1, 2);
        const float inv0 = 1.f / l0;
        const float inv1 = 1.f / l1;
        __half* ob = O +
            (size_t)(b * SEQ + qt * 128 + wid * 32 + f * 16) * D_MODEL + h * HEAD_DIM;
#pragma unroll
        for (int nc2 = 0; nc2 < 4; nc2++) {
            int col = nc2 * 8 + tg * 2;
            *(uint32_t*)(ob + (size_t)g * D_MODEL + col) =
                pack_f16(o[f][nc2][0] * inv0, o[f][nc2][1] * inv0);
            *(uint32_t*)(ob + (size_t)(g + 8) * D_MODEL + col) =
                pack_f16(o[f][nc2][2] * inv1, o[f][nc2][3] * inv1);
        }
    }
}

// ---------------------------------------------------------------------------
extern "C" void kernel_launch(void* const* d_in, const int* in_sizes, int n_in,
                              void* d_out, int out_size) {
    const float* q  = (const float*)d_in[0];
    const float* k  = (const float*)d_in[1];
    const float* v  = (const float*)d_in[2];
    const float* m  = (const float*)d_in[3];
    const float* wq = (const float*)d_in[4];
    const float* bq = (const float*)d_in[5];
    const float* wk = (const float*)d_in[6];
    const float* bk = (const float*)d_in[7];
    const float* wv = (const float*)d_in[8];
    const float* bv = (const float*)d_in[9];
    const float* wo = (const float*)d_in[10];
    const float* bo = (const float*)d_in[11];
    float* out = (float*)d_out;

    __half *gQ, *gK, *gV, *gO;
    int *gPos, *gCnt;
    uint4* gWp;
    cudaGetSymbolAddress((void**)&gQ, g_Qh);
    cudaGetSymbolAddress((void**)&gK, g_Kh);
    cudaGetSymbolAddress((void**)&gV, g_Vh);
    cudaGetSymbolAddress((void**)&gO, g_Oh);
    cudaGetSymbolAddress((void**)&gPos, g_pos);
    cudaGetSymbolAddress((void**)&gCnt, g_cnt);
    cudaGetSymbolAddress((void**)&gWp, g_Wp);

    prep_w<<<513, 256>>>(wq, wk, wv, wo, gWp, m, gPos, gCnt);

    const float qscale = 0.17677669529663687f * 1.4426950408889634f;
    dim3 qkv_grid(D_MODEL / 64, M_TOTAL / 128, 3);  // (4, 128, 3)
    gemm_qkv<<<qkv_grid, 128>>>(q, k, v, gWp, bq, bk, bv, gQ, gK, gV, gPos,
                                qscale);

    dim3 attn_grid(SEQ / 128, BATCH * N_HEADS);   // (16, 64)
    flash_mma<<<attn_grid, 128>>>(gQ, gK, gV, gCnt, gO);

    dim3 out_grid(D_MODEL / 64, M_TOTAL / 128);   // (4, 128)
    gemm_out<<<out_grid, 128>>>(gO, gWp + 3 * WP_MAT_STRIDE, bo, out);
}

// round 17
// speedup vs baseline: 1.1841x; 1.0353x over previous
#include <cuda_runtime.h>
#include <cuda_fp16.h>
#include <math.h>
#include <stdint.h>

#define D_MODEL 256
#define N_HEADS 8
#define HEAD_DIM 32
#define BATCH 8
#define SEQ 2048
#define M_TOTAL (BATCH * SEQ)  // 16384

// Scratch (alloc-free rule: __device__ globals)
__device__ __half g_Qh[M_TOTAL * D_MODEL];
__device__ __half g_Kh[M_TOTAL * D_MODEL];   // compacted keys
__device__ __half g_Vh[M_TOTAL * D_MODEL];   // compacted values
__device__ __half g_Oh[M_TOTAL * D_MODEL];
__device__ int g_pos[SEQ];
__device__ int g_cnt[1];
// Precomputed W fragments: [mat][nb][ks][nc][lane], uint4 = (hi[p0],lo[p0],hi[p0+4],lo[p0+4])
__device__ uint4 g_Wp[4 * 4 * 16 * 8 * 32];
#define WP_MAT_STRIDE (4 * 16 * 8 * 32)

#define V_STRIDE 144  // halves per dim row (72 words == 8 mod 32 -> clean banks)
#define ONES_H2 0x3C003C00u

// ---------------------------------------------------------------------------
// helpers
// ---------------------------------------------------------------------------
__device__ __forceinline__ void mma_f16(float* c, uint32_t a0, uint32_t a1,
                                        uint32_t a2, uint32_t a3,
                                        uint32_t b0, uint32_t b1) {
    asm volatile(
        "mma.sync.aligned.m16n8k16.row.col.f32.f16.f16.f32 "
        "{%0,%1,%2,%3}, {%4,%5,%6,%7}, {%8,%9}, {%0,%1,%2,%3};"
        : "+f"(c[0]), "+f"(c[1]), "+f"(c[2]), "+f"(c[3])
        : "r"(a0), "r"(a1), "r"(a2), "r"(a3), "r"(b0), "r"(b1));
}

__device__ __forceinline__ uint32_t pack_f16(float lo, float hi) {
    uint32_t r;
    asm("cvt.rn.f16x2.f32 %0, %1, %2;" : "=r"(r) : "f"(hi), "f"(lo));
    return r;
}

// two-way fp16 exp2 (packed)
__device__ __forceinline__ uint32_t hex2(uint32_t x) {
    uint32_t r;
    asm("ex2.approx.f16x2 %0, %1;" : "=r"(r) : "r"(x));
    return r;
}

// multiply fp16x2 by 2^-10
__device__ __forceinline__ uint32_t hscale_dn10(uint32_t x) {
    uint32_t r;
    asm("mul.rn.f16x2 %0, %1, %2;" : "=r"(r) : "r"(x), "r"(0x14001400u));
    return r;
}

// ---------------------------------------------------------------------------
// prep_w + mask scan fused. Blocks 0..511: weight fragment prep.
// Block 512: mask scan (pos/cnt).
// ---------------------------------------------------------------------------
__global__ __launch_bounds__(256) void prep_w(const float* __restrict__ wq,
                                              const float* __restrict__ wk,
                                              const float* __restrict__ wv,
                                              const float* __restrict__ wo,
                                              uint4* __restrict__ Wp,
                                              const float* __restrict__ m,
                                              int* __restrict__ pos,
                                              int* __restrict__ cnt) {
    if (blockIdx.x == 512) {
        __shared__ int warpsum[8];
        const int tid = threadIdx.x;
        int keep[8], local[8], s = 0;
#pragma unroll
        for (int i = 0; i < 8; i++) {
            keep[i] = (m[tid * 8 + i] == 0.0f) ? 1 : 0;
            local[i] = s;
            s += keep[i];
        }
        const int lane = tid & 31, w = tid >> 5;
        int x = s;
#pragma unroll
        for (int d = 1; d < 32; d <<= 1) {
            int y = __shfl_up_sync(0xffffffffu, x, d);
            if (lane >= d) x += y;
        }
        if (lane == 31) warpsum[w] = x;
        __syncthreads();
        if (tid == 0) {
            int a = 0;
#pragma unroll
            for (int i = 0; i < 8; i++) {
                int t = warpsum[i];
                warpsum[i] = a;
                a += t;
            }
            *cnt = a;
        }
        __syncthreads();
        const int off = warpsum[w] + x - s;
#pragma unroll
        for (int i = 0; i < 8; i++)
            pos[tid * 8 + i] = keep[i] ? off + local[i] : -1;
        return;
    }

    int idx = blockIdx.x * 256 + threadIdx.x;  // 0..131071
    int mat = idx >> 15;
    int rem = idx & 32767;
    int p = rem >> 8;    // k-pair 0..127
    int n = rem & 255;   // column
    const float* W = (mat == 0) ? wq : (mat == 1) ? wk : (mat == 2) ? wv : wo;
    float w0 = W[(size_t)(2 * p) * 256 + n];
    float w1 = W[(size_t)(2 * p + 1) * 256 + n];
    uint32_t hip = pack_f16(w0, w1);
    __half2 hh = *(__half2*)&hip;
    uint32_t lop = pack_f16((w0 - __half2float(hh.x)) * 1024.0f,
                            (w1 - __half2float(hh.y)) * 1024.0f);
    int ks = p >> 3, q = p & 7;
    int tg = q & 3, sel = q >> 2;
    int nb = n >> 6, nc = (n >> 3) & 7, g = n & 7;
    int lanew = 4 * g + tg;
    uint2* dst = (uint2*)&Wp[(((mat * 4 + nb) * 16 + ks) * 8 + nc) * 32 + lanew];
    dst[sel] = make_uint2(hip, lop);
}

// ---------------------------------------------------------------------------
// Fused QKV projection GEMM, smem-free (R13-measured). blockIdx.z = matrix.
// ---------------------------------------------------------------------------
__global__ __launch_bounds__(128) void gemm_qkv(
    const float* __restrict__ q, const float* __restrict__ k,
    const float* __restrict__ v, const uint4* __restrict__ Wp,
    const float* __restrict__ bq, const float* __restrict__ bk,
    const float* __restrict__ bv, __half* __restrict__ Cq,
    __half* __restrict__ Ck, __half* __restrict__ Cv,
    const int* __restrict__ remap_kv, float qscale) {
    const int mat = blockIdx.z;
    const float* A = (mat == 0) ? q : (mat == 1) ? k : v;
    const float* bias = (mat == 0) ? bq : (mat == 1) ? bk : bv;
    __half* C = (mat == 0) ? Cq : (mat == 1) ? Ck : Cv;
    const int* remap = (mat == 0) ? (const int*)nullptr : remap_kv;
    const float alpha = (mat == 0) ? qscale : 1.0f;

    const int tid = threadIdx.x;
    const int lane = tid & 31;
    const int wid = tid >> 5;
    const int g = lane >> 2;
    const int tg = lane & 3;
    const int m0 = blockIdx.y * 128;
    const int n0 = blockIdx.x * 64;

    const uint4* wp = Wp + (size_t)mat * WP_MAT_STRIDE +
                      (size_t)blockIdx.x * (16 * 8 * 32) + lane;
    const float* ap0 = A + (size_t)(m0 + wid * 32 + g) * 256 + 2 * tg;
    const float* ap1 = ap0 + 8 * 256;
    const float* ap2 = ap0 + 16 * 256;
    const float* ap3 = ap0 + 24 * 256;

    float acc[2][8][4];
#pragma unroll
    for (int f = 0; f < 2; f++)
#pragma unroll
        for (int nc = 0; nc < 8; nc++)
#pragma unroll
            for (int i = 0; i < 4; i++) acc[f][nc][i] = 0.f;

#pragma unroll 4
    for (int ks = 0; ks < 16; ks++) {
        uint32_t a[2][4], sa[2][4];
        {
            float2 x0 = *(const float2*)(ap0 + ks * 16);
            float2 x1 = *(const float2*)(ap1 + ks * 16);
            float2 x2 = *(const float2*)(ap0 + ks * 16 + 8);
            float2 x3 = *(const float2*)(ap1 + ks * 16 + 8);
            a[0][0] = pack_f16(x0.x, x0.y);
            a[0][1] = pack_f16(x1.x, x1.y);
            a[0][2] = pack_f16(x2.x, x2.y);
            a[0][3] = pack_f16(x3.x, x3.y);
            float2 y0 = *(const float2*)(ap2 + ks * 16);
            float2 y1 = *(const float2*)(ap3 + ks * 16);
            float2 y2 = *(const float2*)(ap2 + ks * 16 + 8);
            float2 y3 = *(const float2*)(ap3 + ks * 16 + 8);
            a[1][0] = pack_f16(y0.x, y0.y);
            a[1][1] = pack_f16(y1.x, y1.y);
            a[1][2] = pack_f16(y2.x, y2.y);
            a[1][3] = pack_f16(y3.x, y3.y);
        }
#pragma unroll
        for (int f = 0; f < 2; f++)
#pragma unroll
            for (int i = 0; i < 4; i++) sa[f][i] = hscale_dn10(a[f][i]);

#pragma unroll
        for (int nc = 0; nc < 8; nc++) {
            uint4 w = wp[(ks * 8 + nc) * 32];
#pragma unroll
            for (int f = 0; f < 2; f++) {
                mma_f16(acc[f][nc], sa[f][0], sa[f][1], sa[f][2], sa[f][3],
                        w.y, w.w);
                mma_f16(acc[f][nc], a[f][0], a[f][1], a[f][2], a[f][3],
                        w.x, w.z);
            }
        }
    }

#pragma unroll
    for (int f = 0; f < 2; f++) {
        int r0 = m0 + wid * 32 + f * 16 + g;
        int r1 = r0 + 8;
        int d0 = r0, d1 = r1;
        bool st0 = true, st1 = true;
        if (remap) {
            int p0 = __ldg(remap + (r0 & (SEQ - 1)));
            int p1 = __ldg(remap + (r1 & (SEQ - 1)));
            st0 = p0 >= 0;
            st1 = p1 >= 0;
            d0 = (r0 & ~(SEQ - 1)) + p0;
            d1 = (r1 & ~(SEQ - 1)) + p1;
        }
#pragma unroll
        for (int nc = 0; nc < 8; nc++) {
            int col = n0 + nc * 8 + tg * 2;
            float2 bv2 = *(const float2*)(bias + col);
            if (st0)
                *(uint32_t*)(C + (size_t)d0 * 256 + col) =
                    pack_f16((acc[f][nc][0] + bv2.x) * alpha,
                             (acc[f][nc][1] + bv2.y) * alpha);
            if (st1)
                *(uint32_t*)(C + (size_t)d1 * 256 + col) =
                    pack_f16((acc[f][nc][2] + bv2.x) * alpha,
                             (acc[f][nc][3] + bv2.y) * alpha);
        }
    }
}

// ---------------------------------------------------------------------------
// Output projection GEMM (R13-measured, 128-row tile): A fp16 -> C fp32.
// ---------------------------------------------------------------------------
__global__ __launch_bounds__(128) void gemm_out(const __half* __restrict__ A,
                                                const uint4* __restrict__ Wp,
                                                const float* __restrict__ bias,
                                                float* __restrict__ C) {
    const int tid = threadIdx.x;
    const int lane = tid & 31;
    const int wid = tid >> 5;
    const int g = lane >> 2;
    const int tg = lane & 3;
    const int m0 = blockIdx.y * 128;
    const int n0 = blockIdx.x * 64;

    const uint4* wp = Wp + (size_t)blockIdx.x * (16 * 8 * 32) + lane;
    const __half* ap0 = A + (size_t)(m0 + wid * 32 + g) * 256 + 2 * tg;
    const __half* ap1 = ap0 + 8 * 256;
    const __half* ap2 = ap0 + 16 * 256;
    const __half* ap3 = ap0 + 24 * 256;

    float acc[2][8][4];
#pragma unroll
    for (int f = 0; f < 2; f++)
#pragma unroll
        for (int nc = 0; nc < 8; nc++)
#pragma unroll
            for (int i = 0; i < 4; i++) acc[f][nc][i] = 0.f;

#pragma unroll 4
    for (int ks = 0; ks < 16; ks++) {
        uint32_t a[2][4], sa[2][4];
        a[0][0] = *(const uint32_t*)(ap0 + ks * 16);
        a[0][1] = *(const uint32_t*)(ap1 + ks * 16);
        a[0][2] = *(const uint32_t*)(ap0 + ks * 16 + 8);
        a[0][3] = *(const uint32_t*)(ap1 + ks * 16 + 8);
        a[1][0] = *(const uint32_t*)(ap2 + ks * 16);
        a[1][1] = *(const uint32_t*)(ap3 + ks * 16);
        a[1][2] = *(const uint32_t*)(ap2 + ks * 16 + 8);
        a[1][3] = *(const uint32_t*)(ap3 + ks * 16 + 8);
#pragma unroll
        for (int f = 0; f < 2; f++)
#pragma unroll
            for (int i = 0; i < 4; i++) sa[f][i] = hscale_dn10(a[f][i]);

#pragma unroll
        for (int nc = 0; nc < 8; nc++) {
            uint4 w = wp[(ks * 8 + nc) * 32];
#pragma unroll
            for (int f = 0; f < 2; f++) {
                mma_f16(acc[f][nc], sa[f][0], sa[f][1], sa[f][2], sa[f][3],
                        w.y, w.w);
                mma_f16(acc[f][nc], a[f][0], a[f][1], a[f][2], a[f][3],
                        w.x, w.z);
            }
        }
    }

#pragma unroll
    for (int f = 0; f < 2; f++) {
        int r0 = m0 + wid * 32 + f * 16 + g;
        int r1 = r0 + 8;
#pragma unroll
        for (int nc = 0; nc < 8; nc++) {
            int col = n0 + nc * 8 + tg * 2;
            float2 bv = *(const float2*)(bias + col);
            *(float2*)(C + (size_t)r0 * 256 + col) =
                make_float2(acc[f][nc][0] + bv.x, acc[f][nc][1] + bv.y);
            *(float2*)(C + (size_t)r1 * 256 + col) =
                make_float2(acc[f][nc][2] + bv.x, acc[f][nc][3] + bv.y);
        }
    }
}

// ---------------------------------------------------------------------------
// Flash attention: 128-key tiles; softmax via f16x2 ex2; lr via ones-mma
// (exact fp32 row sums from the tensor pipe, no shfl reduce).
// grid = (SEQ/128, B*H), block = 128 (4 warps). Warp: 32 queries.
// ---------------------------------------------------------------------------
__global__ __launch_bounds__(128) void flash_mma(const __half* __restrict__ Q,
                                                 const __half* __restrict__ K,
                                                 const __half* __restrict__ V,
                                                 const int* __restrict__ cntp,
                                                 __half* __restrict__ O) {
    __shared__ uint32_t Ks32[128 * 16];     // [key][dim-pair-permuted]
    __shared__ __half Vd[32 * V_STRIDE];    // [dim][key-permuted]

    const int tid = threadIdx.x;
    const int lane = tid & 31;
    const int wid = tid >> 5;
    const int g = lane >> 2;
    const int tg = lane & 3;

    const int qt = blockIdx.x;
    const int b = blockIdx.y >> 3;
    const int h = blockIdx.y & 7;

    const int cnt = __ldg(cntp);
    const int nt = (cnt + 127) >> 7;

    uint32_t qf[2][2][4];
#pragma unroll
    for (int f = 0; f < 2; f++) {
        const __half* qb = Q +
            (size_t)(b * SEQ + qt * 128 + wid * 32 + f * 16) * D_MODEL + h * HEAD_DIM;
#pragma unroll
        for (int kc = 0; kc < 2; kc++) {
            qf[f][kc][0] = *(const uint32_t*)(qb + (size_t)g * D_MODEL + kc * 16 + 2 * tg);
            qf[f][kc][1] = *(const uint32_t*)(qb + (size_t)(g + 8) * D_MODEL + kc * 16 + 2 * tg);
            qf[f][kc][2] = *(const uint32_t*)(qb + (size_t)g * D_MODEL + kc * 16 + 8 + 2 * tg);
            qf[f][kc][3] = *(const uint32_t*)(qb + (size_t)(g + 8) * D_MODEL + kc * 16 + 8 + 2 * tg);
        }
    }

    float o[2][4][4];
#pragma unroll
    for (int f = 0; f < 2; f++)
#pragma unroll
        for (int i = 0; i < 4; i++)
#pragma unroll
            for (int j = 0; j < 4; j++) o[f][i][j] = 0.f;
    float lracc[2][4];
#pragma unroll
    for (int f = 0; f < 2; f++)
#pragma unroll
        for (int i = 0; i < 4; i++) lracc[f][i] = 0.f;

    const __half* kbase = K + (size_t)b * SEQ * D_MODEL + h * HEAD_DIM;
    const __half* vbase = V + (size_t)b * SEQ * D_MODEL + h * HEAD_DIM;

    for (int t = 0; t < nt; t++) {
        __syncthreads();
#pragma unroll
        for (int i = 0; i < 8; i++) {
            int item = tid + i * 128;          // 0..1023
            int r = item >> 3, pe = item & 7;  // key row 0..127
            int key = t * 128 + r;
            uint2 kv2 = make_uint2(0u, 0u), vv2 = make_uint2(0u, 0u);
            if (key < cnt) {
                kv2 = *(const uint2*)(kbase + (size_t)key * D_MODEL + pe * 4);
                vv2 = *(const uint2*)(vbase + (size_t)key * D_MODEL + pe * 4);
            }
            int p0 = pe * 2;
            Ks32[r * 16 + (p0 & 3) * 4 + (p0 >> 2)] = kv2.x;
            int p1 = p0 + 1;
            Ks32[r * 16 + (p1 & 3) * 4 + (p1 >> 2)] = kv2.y;
            int grp = r >> 4, u = r & 15, kp = u >> 1, odd = u & 1;
            int phi = grp * 16 + ((kp & 3) * 2 + (kp >> 2)) * 2 + odd;
            __half2 va = *(__half2*)&vv2.x;
            __half2 vb2 = *(__half2*)&vv2.y;
            int d0 = pe * 4;
            Vd[(d0 + 0) * V_STRIDE + phi] = va.x;
            Vd[(d0 + 1) * V_STRIDE + phi] = va.y;
            Vd[(d0 + 2) * V_STRIDE + phi] = vb2.x;
            Vd[(d0 + 3) * V_STRIDE + phi] = vb2.y;
        }
        __syncthreads();

        const bool fix = (t == nt - 1) && (cnt & 127);
#pragma unroll
        for (int pc = 0; pc < 8; pc++) {
            uint4 kf0 = *(const uint4*)&Ks32[(pc * 16 + g) * 16 + 4 * tg];
            uint4 kf1 = *(const uint4*)&Ks32[(pc * 16 + 8 + g) * 16 + 4 * tg];

            uint32_t ph[2][4];
#pragma unroll
            for (int f = 0; f < 2; f++) {
                float s0[4] = {0.f, 0.f, 0.f, 0.f};
                float s1[4] = {0.f, 0.f, 0.f, 0.f};
                mma_f16(s0, qf[f][0][0], qf[f][0][1], qf[f][0][2], qf[f][0][3],
                        kf0.x, kf0.y);
                mma_f16(s0, qf[f][1][0], qf[f][1][1], qf[f][1][2], qf[f][1][3],
                        kf0.z, kf0.w);
                mma_f16(s1, qf[f][0][0], qf[f][0][1], qf[f][0][2], qf[f][0][3],
                        kf1.x, kf1.y);
                mma_f16(s1, qf[f][1][0], qf[f][1][1], qf[f][1][2], qf[f][1][3],
                        kf1.z, kf1.w);
                if (fix) {
                    int key0 = t * 128 + pc * 16 + 2 * tg;
                    if (key0 >= cnt) { s0[0] = -1e30f; s0[2] = -1e30f; }
                    if (key0 + 1 >= cnt) { s0[1] = -1e30f; s0[3] = -1e30f; }
                    int key1 = key0 + 8;
                    if (key1 >= cnt) { s1[0] = -1e30f; s1[2] = -1e30f; }
                    if (key1 + 1 >= cnt) { s1[1] = -1e30f; s1[3] = -1e30f; }
                }
                // pack scores -> fp16x2, two-way exp2 on packed halves
                ph[f][0] = hex2(pack_f16(s0[0], s0[1]));
                ph[f][1] = hex2(pack_f16(s0[2], s0[3]));
                ph[f][2] = hex2(pack_f16(s1[0], s1[1]));
                ph[f][3] = hex2(pack_f16(s1[2], s1[3]));
                // row sums of P on the tensor pipe (B = ones)
                mma_f16(lracc[f], ph[f][0], ph[f][1], ph[f][2], ph[f][3],
                        ONES_H2, ONES_H2);
            }

#pragma unroll
            for (int nc2 = 0; nc2 < 4; nc2++) {
                uint2 vb = *(const uint2*)&Vd[(nc2 * 8 + g) * V_STRIDE + pc * 16 + 4 * tg];
                mma_f16(o[0][nc2], ph[0][0], ph[0][1], ph[0][2], ph[0][3],
                        vb.x, vb.y);
                mma_f16(o[1][nc2], ph[1][0], ph[1][1], ph[1][2], ph[1][3],
                        vb.x, vb.y);
            }
        }
    }

#pragma unroll
    for (int f = 0; f < 2; f++) {
        const float inv0 = 1.f / lracc[f][0];  // row g sum
        const float inv1 = 1.f / lracc[f][2];  // row g+8 sum
        __half* ob = O +
            (size_t)(b * SEQ + qt * 128 + wid * 32 + f * 16) * D_MODEL + h * HEAD_DIM;
#pragma unroll
        for (int nc2 = 0; nc2 < 4; nc2++) {
            int col = nc2 * 8 + tg * 2;
            *(uint32_t*)(ob + (size_t)g * D_MODEL + col) =
                pack_f16(o[f][nc2][0] * inv0, o[f][nc2][1] * inv0);
            *(uint32_t*)(ob + (size_t)(g + 8) * D_MODEL + col) =
                pack_f16(o[f][nc2][2] * inv1, o[f][nc2][3] * inv1);
        }
    }
}

// ---------------------------------------------------------------------------
extern "C" void kernel_launch(void* const* d_in, const int* in_sizes, int n_in,
                              void* d_out, int out_size) {
    const float* q  = (const float*)d_in[0];
    const float* k  = (const float*)d_in[1];
    const float* v  = (const float*)d_in[2];
    const float* m  = (const float*)d_in[3];
    const float* wq = (const float*)d_in[4];
    const float* bq = (const float*)d_in[5];
    const float* wk = (const float*)d_in[6];
    const float* bk = (const float*)d_in[7];
    const float* wv = (const float*)d_in[8];
    const float* bv = (const float*)d_in[9];
    const float* wo = (const float*)d_in[10];
    const float* bo = (const float*)d_in[11];
    float* out = (float*)d_out;

    __half *gQ, *gK, *gV, *gO;
    int *gPos, *gCnt;
    uint4* gWp;
    cudaGetSymbolAddress((void**)&gQ, g_Qh);
    cudaGetSymbolAddress((void**)&gK, g_Kh);
    cudaGetSymbolAddress((void**)&gV, g_Vh);
    cudaGetSymbolAddress((void**)&gO, g_Oh);
    cudaGetSymbolAddress((void**)&gPos, g_pos);
    cudaGetSymbolAddress((void**)&gCnt, g_cnt);
    cudaGetSymbolAddress((void**)&gWp, g_Wp);

    prep_w<<<513, 256>>>(wq, wk, wv, wo, gWp, m, gPos, gCnt);

    const float qscale = 0.17677669529663687f * 1.4426950408889634f;
    dim3 qkv_grid(D_MODEL / 64, M_TOTAL / 128, 3);  // (4, 128, 3)
    gemm_qkv<<<qkv_grid, 128>>>(q, k, v, gWp, bq, bk, bv, gQ, gK, gV, gPos,
                                qscale);

    dim3 attn_grid(SEQ / 128, BATCH * N_HEADS);   // (16, 64)
    flash_mma<<<attn_grid, 128>>>(gQ, gK, gV, gCnt, gO);

    dim3 out_grid(D_MODEL / 64, M_TOTAL / 128);   // (4, 128)
    gemm_out<<<out_grid, 128>>>(gO, gWp + 3 * WP_MAT_STRIDE, bo, out);
}